// round 15
// baseline (speedup 1.0000x reference)
#include <cuda_runtime.h>
#include <cuda_bf16.h>
#include <cstdint>

#define D        100
#define D4       25
#define KCODES   512
#define NKSTEP   7              // K = 112 (pad 100 -> 112), 7 steps of k16
#define STRW     60             // A row stride in 32-bit words (= 120 bf16)
#define TM       128            // points per block
#define CN       32             // codes per chunk
#define NCHUNK   16
#define CHUNKW   (NKSTEP*CN*8)  // 1792 words per chunk (fragment-major)
#define CHUNKB   (CHUNKW*4)     // 7168 bytes
#define THREADS  256
#define NBLOCKS  2048
#define NPTS     (NBLOCKS*TM)
#define EPS      1e-3f
#define LCAP     16             // candidate list capacity per row

__device__ float g_partial[NBLOCKS];
__device__ float g_ee[KCODES];
__device__ int   g_bidx[NPTS];
// fragment-major bf16 codebook: per 32-code chunk,
// word w = (ks*32 + code)*8 + rr, rr = qt*2+h holds original k-word
// o = ks*8 + qt + 4*h (bf16 elems 2o, 2o+1; zero-padded past D)
__device__ __align__(16) uint32_t g_bb[NCHUNK * CHUNKW];

// ---- selection-kernel smem byte offsets ----
#define OFF_B     0         // 2 x 7168 = 14336 (double-buffered chunk)
#define OFF_A     14336     // 128*60*4 = 30720
#define OFF_LIST  45056     // 128*16*4 = 8192
#define OFF_XX    53248     // 128 f32
#define OFF_EE    53760     // 512 f32
#define OFF_CNT   55808     // 128 i32
#define OFF_MBAR  56320     // 2 x u64 mbarriers
#define SMEM_BYTES 56336

__device__ __forceinline__ uint32_t pack_bf16x2(float lo, float hi) {
    __nv_bfloat162 h = __floats2bfloat162_rn(lo, hi);
    return *reinterpret_cast<uint32_t*>(&h);
}
__device__ __forceinline__ uint32_t smem_u32(const void* p) {
    uint32_t a;
    asm("{ .reg .u64 t; cvta.to.shared.u64 t, %1; cvt.u32.u64 %0, t; }"
        : "=r"(a) : "l"(p));
    return a;
}

#define MBAR_INIT(addr) \
    asm volatile("mbarrier.init.shared.b64 [%0], 1;" :: "r"(addr) : "memory")
#define MBAR_EXPECT_TX(addr, bytes) \
    asm volatile("mbarrier.arrive.expect_tx.shared.b64 _, [%0], %1;" \
                 :: "r"(addr), "r"(bytes) : "memory")
#define CP_BULK(dst_u32, src_ptr, bytes, mbar_u32) \
    asm volatile("cp.async.bulk.shared::cta.global.mbarrier::complete_tx::bytes " \
                 "[%0], [%1], %2, [%3];" \
                 :: "r"(dst_u32), "l"(src_ptr), "r"(bytes), "r"(mbar_u32) : "memory")
#define MBAR_WAIT(addr, phase) \
    asm volatile("{\n\t.reg .pred P;\n" \
                 "W%=:\n\tmbarrier.try_wait.parity.shared.b64 P, [%0], %1;\n\t" \
                 "@!P bra W%=;\n\t}" :: "r"(addr), "r"(phase) : "memory")

#define MMA_BF16(acc, av0, av1, bv) \
    asm volatile( \
        "mma.sync.aligned.m16n8k16.row.col.f32.bf16.bf16.f32 " \
        "{%0,%1,%2,%3}, {%4,%5,%6,%7}, {%8,%9}, {%0,%1,%2,%3};" \
        : "+f"((acc)[0]), "+f"((acc)[1]), "+f"((acc)[2]), "+f"((acc)[3]) \
        : "r"((av0).x), "r"((av1).x), "r"((av0).y), "r"((av1).y), \
          "r"((bv).x), "r"((bv).y))

// paired destination word index for original word o (o in 0..55) — A tile only
__device__ __forceinline__ int pair_d(int o) {
    int ks = o >> 3, r = o & 7;
    return (r < 4) ? (ks * 8 + 2 * r) : (ks * 8 + 2 * (r - 4) + 1);
}

// exact fp32 dot, sequential k-ascending fmaf (reference accumulation order)
__device__ __noinline__ float exact_dot(const float* __restrict__ a,
                                        const float* __restrict__ b) {
    float acc = 0.0f;
    #pragma unroll
    for (int k4 = 0; k4 < D4; k4++) {
        float4 av = ((const float4*)a)[k4];
        float4 bv = ((const float4*)b)[k4];
        acc = fmaf(av.x, bv.x, acc);
        acc = fmaf(av.y, bv.y, acc);
        acc = fmaf(av.z, bv.z, acc);
        acc = fmaf(av.w, bv.w, acc);
    }
    return acc;
}

// ---------------- prep: fragment-major bf16 codebook + exact ||e||^2 --------
__global__ void prep_kernel(const float* __restrict__ emb) {
    int c = blockIdx.x * blockDim.x + threadIdx.x;
    if (c >= KCODES) return;
    const float* er = emb + (size_t)c * D;
    float s = 0.0f;
    for (int k = 0; k < D; k++) s = fmaf(er[k], er[k], s);  // reference order
    g_ee[c] = s;

    const int ch = c >> 5, cl = c & 31;
    uint32_t* base = g_bb + (size_t)ch * CHUNKW;
    for (int ks = 0; ks < NKSTEP; ks++) {
        for (int rr = 0; rr < 8; rr++) {
            int qt = rr >> 1, h = rr & 1;
            int o = ks * 8 + qt + 4 * h;       // original k-word
            int e0 = 2 * o, e1 = 2 * o + 1;
            float f0 = (e0 < D) ? er[e0] : 0.0f;
            float f1 = (e1 < D) ? er[e1] : 0.0f;
            base[(ks * CN + cl) * 8 + rr] = pack_bf16x2(f0, f1);
        }
    }
}

// profiling-alignment no-op (ncu profiles global launch #4 -> make it vq)
__global__ void dummy_kernel() {}

// ---------------- selection kernel: argmin codes -> g_bidx ----------------
__global__ void __launch_bounds__(THREADS, 3)
vq_kernel(const float* __restrict__ x,
          const float* __restrict__ emb)
{
    extern __shared__ char smc[];
    uint32_t* Bw   = (uint32_t*)(smc + OFF_B);    // 2 buffers of CHUNKW words
    uint32_t* Aw   = (uint32_t*)(smc + OFF_A);
    int*      list = (int*)     (smc + OFF_LIST);
    float*    xx   = (float*)   (smc + OFF_XX);
    float*    ee_s = (float*)   (smc + OFF_EE);
    int*      cnt  = (int*)     (smc + OFF_CNT);

    const int tid  = threadIdx.x;
    const int wid  = tid >> 5;
    const int lane = tid & 31;
    const int g    = lane >> 2;   // groupID 0..7
    const int qt   = lane & 3;    // thread-in-group 0..3
    const int pt0  = blockIdx.x * TM;
    const uint32_t bsm  = smem_u32(Bw);
    const uint32_t mbar = smem_u32(smc + OFF_MBAR);

    // ---- init mbarriers ----
    if (tid == 0) {
        MBAR_INIT(mbar);
        MBAR_INIT(mbar + 8);
    }
    // ---- zero A pad words, counters; copy ||e||^2 ----
    for (int i = tid; i < TM * STRW; i += THREADS) Aw[i] = 0u;
    if (tid < TM) cnt[tid] = 0;
    for (int i = tid; i < KCODES; i += THREADS) ee_s[i] = g_ee[i];
    __syncthreads();    // mbarriers initialized, visible to all

    if (tid == 0) {
        MBAR_EXPECT_TX(mbar, CHUNKB);
        CP_BULK(bsm, (const char*)g_bb, CHUNKB, mbar);
    }

    // ---- build A tile (paired layout), coalesced x reads (warms L2) ----
    for (int i = tid; i < TM * D4; i += THREADS) {
        int pt = i / D4, k4 = i % D4;
        float4 f = ((const float4*)x)[(size_t)(pt0 + pt) * D4 + k4];
        int o0 = 2 * k4, o1 = 2 * k4 + 1;
        Aw[pt * STRW + pair_d(o0)] = pack_bf16x2(f.x, f.y);
        Aw[pt * STRW + pair_d(o1)] = pack_bf16x2(f.z, f.w);
    }

    // ---- exact ||x||^2 (sequential k, reference order; x now L2-hot) ----
    if (tid < TM) {
        const float4* xr = (const float4*)(x + (size_t)(pt0 + tid) * D);
        float s = 0.0f;
        #pragma unroll
        for (int k4 = 0; k4 < D4; k4++) {
            float4 v = xr[k4];
            s = fmaf(v.x, v.x, s);
            s = fmaf(v.y, v.y, s);
            s = fmaf(v.z, v.z, s);
            s = fmaf(v.w, v.w, s);
        }
        xx[tid] = s;
    }
    __syncthreads();   // A tile complete; chunk-0 bulk copy in flight

    // ---- hoist A fragments for all 7 k-steps into registers ----
    const int m0 = wid * 16;
    const int r0 = m0 + g, r1 = m0 + g + 8;
    const uint32_t* Ar0 = Aw + r0 * STRW + qt * 2;
    const uint32_t* Ar1 = Aw + r1 * STRW + qt * 2;
    uint2 afr0[NKSTEP], afr1[NKSTEP];
    #pragma unroll
    for (int ks = 0; ks < NKSTEP; ks++) {
        afr0[ks] = *(const uint2*)(Ar0 + ks * 8);   // (a0, a2)
        afr1[ks] = *(const uint2*)(Ar1 + ks * 8);   // (a1, a3)
    }
    const float xx0 = xx[r0], xx1 = xx[r1];

    float run0 = 3.4e38f, run1 = 3.4e38f;

    #pragma unroll 1
    for (int ch = 0; ch < NCHUNK; ch++) {
        // data for chunk ch ready?
        MBAR_WAIT(mbar + (ch & 1) * 8, (ch >> 1) & 1);
        __syncthreads();    // all warps past chunk ch-1 -> buffer (ch+1)&1 free

        // issue bulk copy for chunk ch+1 (overlaps compute below)
        if (tid == 0 && ch + 1 < NCHUNK) {
            uint32_t mb = mbar + ((ch + 1) & 1) * 8;
            MBAR_EXPECT_TX(mb, CHUNKB);
            CP_BULK(bsm + ((ch + 1) & 1) * CHUNKB,
                    (const char*)(g_bb + (size_t)(ch + 1) * CHUNKW),
                    CHUNKB, mb);
        }

        const int cbase = ch * CN;
        // lane-invariant fragment base: conflict-free banks (8g + 2qt)
        const uint32_t* Bfrag = Bw + (ch & 1) * CHUNKW + g * 8 + qt * 2;

        float acc[4][4];
        #pragma unroll
        for (int t = 0; t < 4; t++)
            #pragma unroll
            for (int j = 0; j < 4; j++) acc[t][j] = 0.0f;

        #pragma unroll
        for (int ks = 0; ks < NKSTEP; ks++) {
            const uint2 av0 = afr0[ks];
            const uint2 av1 = afr1[ks];
            const uint32_t* Bks = Bfrag + ks * (CN * 8);
            #pragma unroll
            for (int t = 0; t < 4; t++) {
                uint2 bv = *(const uint2*)(Bks + t * 64);
                MMA_BF16(acc[t], av0, av1, bv);
            }
        }

        // ---- approx distances + row-wide chunk min ----
        float ch0 = 3.4e38f, ch1 = 3.4e38f;
        #pragma unroll
        for (int t = 0; t < 4; t++) {
            float2 ev = *(const float2*)&ee_s[cbase + 8 * t + 2 * qt];
            #pragma unroll
            for (int j = 0; j < 2; j++) {
                float e = (j == 0) ? ev.x : ev.y;
                float d0 = (xx0 + e) - 2.0f * acc[t][j];
                float d1 = (xx1 + e) - 2.0f * acc[t][2 + j];
                acc[t][j] = d0; acc[t][2 + j] = d1;
                ch0 = fminf(ch0, d0); ch1 = fminf(ch1, d1);
            }
        }
        #pragma unroll
        for (int off = 1; off <= 2; off <<= 1) {
            ch0 = fminf(ch0, __shfl_xor_sync(0xFFFFFFFFu, ch0, off));
            ch1 = fminf(ch1, __shfl_xor_sync(0xFFFFFFFFu, ch1, off));
        }
        run0 = fminf(run0, ch0);
        run1 = fminf(run1, ch1);
        const float thr0 = run0 + EPS, thr1 = run1 + EPS;

        // ---- push candidates (deferred rescore) ----
        #pragma unroll
        for (int t = 0; t < 4; t++) {
            #pragma unroll
            for (int j = 0; j < 2; j++) {
                int col = cbase + 8 * t + 2 * qt + j;
                if (acc[t][j] <= thr0) {
                    int p = atomicAdd(&cnt[r0], 1);
                    if (p < LCAP) list[r0 * LCAP + p] = col;
                }
                if (acc[t][2 + j] <= thr1) {
                    int p = atomicAdd(&cnt[r1], 1);
                    if (p < LCAP) list[r1 * LCAP + p] = col;
                }
            }
        }
    }
    __syncthreads();

    // ---- rescore phase: one thread per row, exact fp32 over candidates ----
    if (tid < TM) {
        const int row = tid;
        const float xxv = xx[row];
        const float* xr = x + (size_t)(pt0 + row) * D;   // L2-hot
        float best = 3.4e38f;
        int besti = 0x7fffffff;
        int n = cnt[row];
        if (n <= LCAP) {
            for (int i = 0; i < n; i++) {
                int col = list[row * LCAP + i];
                float t = xxv + ee_s[col];
                float dex = t - 2.0f * exact_dot(xr, emb + (size_t)col * D);
                if (dex < best || (dex == best && col < besti)) {
                    best = dex; besti = col;
                }
            }
        } else {
            // overflow fallback (astronomically rare): exact scan of all codes
            for (int col = 0; col < KCODES; col++) {
                float t = xxv + ee_s[col];
                float dex = t - 2.0f * exact_dot(xr, emb + (size_t)col * D);
                if (dex < best || (dex == best && col < besti)) {
                    best = dex; besti = col;
                }
            }
        }
        g_bidx[pt0 + row] = besti;
    }
}

// ------- output kernel: straight-through quantized output + loss partials ---
__global__ void __launch_bounds__(THREADS)
out_kernel(const float* __restrict__ x,
           const float* __restrict__ emb,
           float* __restrict__ out)
{
    __shared__ int   bsh[TM];
    __shared__ float red[THREADS];

    const int tid = threadIdx.x;
    const int pt0 = blockIdx.x * TM;

    if (tid < TM) bsh[tid] = g_bidx[pt0 + tid];
    __syncthreads();

    // identical assignment + arithmetic order to the previously fused phase 3
    float lsum = 0.0f;
    for (int idx = tid; idx < TM * D4; idx += THREADS) {
        int pt = idx / D4;
        int k4 = idx % D4;
        int best = bsh[pt];
        float4 xg = ((const float4*)x)[(size_t)(pt0 + pt) * D4 + k4];
        float4 eg = ((const float4*)(emb + (size_t)best * D))[k4];
        float4 o;
        float dd;
        dd = eg.x - xg.x; o.x = xg.x + dd; lsum = fmaf(dd, dd, lsum);
        dd = eg.y - xg.y; o.y = xg.y + dd; lsum = fmaf(dd, dd, lsum);
        dd = eg.z - xg.z; o.z = xg.z + dd; lsum = fmaf(dd, dd, lsum);
        dd = eg.w - xg.w; o.w = xg.w + dd; lsum = fmaf(dd, dd, lsum);
        ((float4*)out)[(size_t)pt0 * D4 + idx] = o;
    }

    red[tid] = lsum;
    __syncthreads();
    #pragma unroll
    for (int s = 128; s > 0; s >>= 1) {
        if (tid < s) red[tid] += red[tid + s];
        __syncthreads();
    }
    if (tid == 0) g_partial[blockIdx.x] = red[0];
}

__global__ void loss_kernel(float* __restrict__ out, int nblocks,
                            long long nelem, long long nq)
{
    __shared__ double dred[256];
    double s = 0.0;
    for (int i = threadIdx.x; i < nblocks; i += 256)
        s += (double)g_partial[i];
    dred[threadIdx.x] = s;
    __syncthreads();
    #pragma unroll
    for (int st = 128; st > 0; st >>= 1) {
        if (threadIdx.x < st) dred[threadIdx.x] += dred[threadIdx.x + st];
        __syncthreads();
    }
    if (threadIdx.x == 0) {
        double mean = dred[0] / (double)nelem;
        out[nq]     = (float)mean;          // quantization_loss
        out[nq + 1] = (float)(0.25 * mean); // commitment_loss
    }
}

extern "C" void kernel_launch(void* const* d_in, const int* in_sizes, int n_in,
                              void* d_out, int out_size)
{
    const float* x   = (const float*)d_in[0];   // [N, 100]
    const float* emb = (const float*)d_in[1];   // [512, 100]
    float* out = (float*)d_out;

    long long nelem = in_sizes[0];              // 26214400
    int npts = (int)(nelem / D);                // 262144
    int nblocks = npts / TM;                    // 2048

    cudaFuncSetAttribute(vq_kernel,
                         cudaFuncAttributeMaxDynamicSharedMemorySize,
                         SMEM_BYTES);

    prep_kernel<<<2, 256>>>(emb);
    dummy_kernel<<<1, 32>>>();   // ncu profiles global launch #4 ...
    dummy_kernel<<<1, 32>>>();   // ... make that launch vq_kernel
    vq_kernel<<<nblocks, THREADS, SMEM_BYTES>>>(x, emb);
    out_kernel<<<nblocks, THREADS>>>(x, emb, out);
    loss_kernel<<<1, 256>>>(out, nblocks, nelem, nelem);
}

// round 17
// speedup vs baseline: 1.1022x; 1.1022x over previous
#include <cuda_runtime.h>
#include <cuda_bf16.h>
#include <cstdint>

#define D        100
#define D4       25
#define KCODES   512
#define NKSTEP   7              // K = 112 (pad 100 -> 112)
#define CN       64             // codes per chunk
#define NCHUNK   8
#define CHUNKW   (NKSTEP*CN*8)  // 3584 words per chunk (fragment-major)
#define BWORDS   (NCHUNK*CHUNKW)// 28672 words = 114688 B, full codebook
#define TM       256            // points per tile (16 warps x 16 rows)
#define THREADS  512
#define NTILES   1024
#define OTM      128            // out-kernel tile
#define OBLOCKS  2048
#define EPS      1e-3f
#define LCAP     16

__device__ float g_partial[OBLOCKS];
__device__ float g_ee[KCODES];
__device__ int   g_bidx[NTILES * TM];
// fragment-major bf16 codebook: per 64-code chunk,
// word w = (ks*64 + code)*8 + rr, rr = qt*2+h holds original k-word
// o = ks*8 + qt + 4*h (bf16 elems 2o, 2o+1; zero-padded past D)
__device__ __align__(16) uint32_t g_bb[BWORDS];

// ---- selection-kernel smem byte offsets ----
#define OFF_B     0         // 114688 B: full resident codebook
#define OFF_EE    114688    // 512 f32
#define OFF_LIST  116736    // 256*16*4 = 16384
#define OFF_CNT   133120    // 256 i32
#define SMEM_BYTES 134144

__device__ __forceinline__ uint32_t pack_bf16x2(float lo, float hi) {
    __nv_bfloat162 h = __floats2bfloat162_rn(lo, hi);
    return *reinterpret_cast<uint32_t*>(&h);
}

#define MMA_BF16(acc, av0, av1, bv) \
    asm volatile( \
        "mma.sync.aligned.m16n8k16.row.col.f32.bf16.bf16.f32 " \
        "{%0,%1,%2,%3}, {%4,%5,%6,%7}, {%8,%9}, {%0,%1,%2,%3};" \
        : "+f"((acc)[0]), "+f"((acc)[1]), "+f"((acc)[2]), "+f"((acc)[3]) \
        : "r"((av0).x), "r"((av1).x), "r"((av0).y), "r"((av1).y), \
          "r"((bv).x), "r"((bv).y))

// exact fp32 dot, sequential k-ascending fmaf (reference accumulation order)
__device__ __forceinline__ float exact_dot(const float* __restrict__ a,
                                           const float* __restrict__ b) {
    float acc = 0.0f;
    #pragma unroll
    for (int k4 = 0; k4 < D4; k4++) {
        float4 av = ((const float4*)a)[k4];
        float4 bv = ((const float4*)b)[k4];
        acc = fmaf(av.x, bv.x, acc);
        acc = fmaf(av.y, bv.y, acc);
        acc = fmaf(av.z, bv.z, acc);
        acc = fmaf(av.w, bv.w, acc);
    }
    return acc;
}

// ---------------- prep: fragment-major bf16 codebook + exact ||e||^2 --------
__global__ void prep_kernel(const float* __restrict__ emb) {
    int c = blockIdx.x * blockDim.x + threadIdx.x;
    if (c >= KCODES) return;
    const float* er = emb + (size_t)c * D;
    float s = 0.0f;
    for (int k = 0; k < D; k++) s = fmaf(er[k], er[k], s);  // reference order
    g_ee[c] = s;

    const int ch = c >> 6, cl = c & 63;
    uint32_t* base = g_bb + (size_t)ch * CHUNKW;
    for (int ks = 0; ks < NKSTEP; ks++) {
        for (int rr = 0; rr < 8; rr++) {
            int qt = rr >> 1, h = rr & 1;
            int o = ks * 8 + qt + 4 * h;       // original k-word
            int e0 = 2 * o, e1 = 2 * o + 1;
            float f0 = (e0 < D) ? er[e0] : 0.0f;
            float f1 = (e1 < D) ? er[e1] : 0.0f;
            base[(ks * CN + cl) * 8 + rr] = pack_bf16x2(f0, f1);
        }
    }
}

// profiling-alignment no-op (ncu profiles global launch #4 -> make it vq)
__global__ void dummy_kernel() {}

// -------- persistent selection kernel: argmin codes -> g_bidx --------------
__global__ void __launch_bounds__(THREADS, 1)
vq_kernel(const float* __restrict__ x,
          const float* __restrict__ emb,
          int ntiles)
{
    extern __shared__ char smc[];
    uint32_t* Bw   = (uint32_t*)(smc + OFF_B);
    float*    ee_s = (float*)   (smc + OFF_EE);
    int*      list = (int*)     (smc + OFF_LIST);
    int*      cnt  = (int*)     (smc + OFF_CNT);

    const int tid  = threadIdx.x;
    const int wid  = tid >> 5;
    const int lane = tid & 31;
    const int g    = lane >> 2;   // groupID 0..7
    const int qt   = lane & 3;    // thread-in-group 0..3
    const int m0   = wid * 16;    // this warp's 16 local rows

    // ---- stage full codebook + ee once ----
    {
        const uint4* src = (const uint4*)g_bb;
        uint4* dst = (uint4*)Bw;
        for (int i = tid; i < BWORDS / 4; i += THREADS) dst[i] = src[i];
        for (int i = tid; i < KCODES; i += THREADS) ee_s[i] = g_ee[i];
    }
    __syncthreads();   // the ONLY block barrier

    const uint32_t* Bfrag = Bw + g * 8 + qt * 2;   // lane fragment base

    // ---- persistent tile loop: warps fully autonomous ----
    for (int tile = blockIdx.x; tile < ntiles; tile += gridDim.x) {
        const int pt0 = tile * TM;
        const int r0 = m0 + g, r1 = r0 + 8;        // local rows

        __syncwarp();                  // prior tile's rescore done
        if (lane < 16) cnt[m0 + lane] = 0;

        // ---- exact ||x||^2: lanes 0-15, one row each (reference order) ----
        float xxl = 0.0f;
        if (lane < 16) {
            const float4* xr = (const float4*)(x + (size_t)(pt0 + m0 + lane) * D);
            #pragma unroll
            for (int k4 = 0; k4 < D4; k4++) {
                float4 v = xr[k4];
                xxl = fmaf(v.x, v.x, xxl);
                xxl = fmaf(v.y, v.y, xxl);
                xxl = fmaf(v.z, v.z, xxl);
                xxl = fmaf(v.w, v.w, xxl);
            }
        }
        __syncwarp();
        const float xx0 = __shfl_sync(0xFFFFFFFFu, xxl, g);
        const float xx1 = __shfl_sync(0xFFFFFFFFu, xxl, g + 8);

        // ---- A fragments straight from gmem (fp32 -> bf16, zero-pad) ----
        const float* xp0 = x + (size_t)(pt0 + r0) * D;
        const float* xp1 = x + (size_t)(pt0 + r1) * D;
        uint2 afr0[NKSTEP], afr1[NKSTEP];
        #pragma unroll
        for (int ks = 0; ks < NKSTEP; ks++) {
            int k0 = ks * 16 + qt * 2;
            int k1 = k0 + 8;
            uint32_t a00 = 0, a01 = 0, a10 = 0, a11 = 0;
            if (k0 < D) {
                float2 v0 = *(const float2*)(xp0 + k0);
                float2 v1 = *(const float2*)(xp1 + k0);
                a00 = pack_bf16x2(v0.x, v0.y);
                a10 = pack_bf16x2(v1.x, v1.y);
            }
            if (k1 < D) {
                float2 v0 = *(const float2*)(xp0 + k1);
                float2 v1 = *(const float2*)(xp1 + k1);
                a01 = pack_bf16x2(v0.x, v0.y);
                a11 = pack_bf16x2(v1.x, v1.y);
            }
            afr0[ks].x = a00; afr0[ks].y = a01;
            afr1[ks].x = a10; afr1[ks].y = a11;
        }

        float run0 = 3.4e38f, run1 = 3.4e38f;

        #pragma unroll 1
        for (int ch = 0; ch < NCHUNK; ch++) {
            const int cbase = ch * CN;
            const uint32_t* Bch = Bfrag + ch * CHUNKW;

            float acc[8][4];
            #pragma unroll
            for (int t = 0; t < 8; t++)
                #pragma unroll
                for (int j = 0; j < 4; j++) acc[t][j] = 0.0f;

            #pragma unroll
            for (int ks = 0; ks < NKSTEP; ks++) {
                const uint2 av0 = afr0[ks];
                const uint2 av1 = afr1[ks];
                const uint32_t* Bks = Bch + ks * (CN * 8);
                #pragma unroll
                for (int t = 0; t < 8; t++) {
                    uint2 bv = *(const uint2*)(Bks + t * 64);
                    MMA_BF16(acc[t], av0, av1, bv);
                }
            }

            // ---- approx distances + row-wide chunk min ----
            float ch0 = 3.4e38f, ch1 = 3.4e38f;
            #pragma unroll
            for (int t = 0; t < 8; t++) {
                float2 ev = *(const float2*)&ee_s[cbase + 8 * t + 2 * qt];
                #pragma unroll
                for (int j = 0; j < 2; j++) {
                    float e = (j == 0) ? ev.x : ev.y;
                    float d0 = (xx0 + e) - 2.0f * acc[t][j];
                    float d1 = (xx1 + e) - 2.0f * acc[t][2 + j];
                    acc[t][j] = d0; acc[t][2 + j] = d1;
                    ch0 = fminf(ch0, d0); ch1 = fminf(ch1, d1);
                }
            }
            #pragma unroll
            for (int off = 1; off <= 2; off <<= 1) {
                ch0 = fminf(ch0, __shfl_xor_sync(0xFFFFFFFFu, ch0, off));
                ch1 = fminf(ch1, __shfl_xor_sync(0xFFFFFFFFu, ch1, off));
            }
            run0 = fminf(run0, ch0);
            run1 = fminf(run1, ch1);
            const float thr0 = run0 + EPS, thr1 = run1 + EPS;

            // ---- push candidates (warp-private rows; deferred rescore) ----
            #pragma unroll
            for (int t = 0; t < 8; t++) {
                #pragma unroll
                for (int j = 0; j < 2; j++) {
                    int col = cbase + 8 * t + 2 * qt + j;
                    if (acc[t][j] <= thr0) {
                        int p = atomicAdd(&cnt[r0], 1);
                        if (p < LCAP) list[r0 * LCAP + p] = col;
                    }
                    if (acc[t][2 + j] <= thr1) {
                        int p = atomicAdd(&cnt[r1], 1);
                        if (p < LCAP) list[r1 * LCAP + p] = col;
                    }
                }
            }
        }
        __syncwarp();   // pushes visible to rescoring lanes

        // ---- rescore: lanes 0-15, one row each, exact fp32, 2-way ILP ----
        if (lane < 16) {
            const int row = m0 + lane;
            const float xv = xxl;      // this lane's own ||x||^2
            const float* xr = x + (size_t)(pt0 + row) * D;
            float best = 3.4e38f;
            int besti = 0x7fffffff;
            int n = cnt[row];
            if (n <= LCAP) {
                int i = 0;
                for (; i + 1 < n; i += 2) {
                    int ca = list[row * LCAP + i];
                    int cb = list[row * LCAP + i + 1];
                    const float* ea = emb + (size_t)ca * D;
                    const float* eb = emb + (size_t)cb * D;
                    float aa = 0.0f, ab = 0.0f;
                    #pragma unroll
                    for (int k4 = 0; k4 < D4; k4++) {
                        float4 xv4 = ((const float4*)xr)[k4];
                        float4 av4 = ((const float4*)ea)[k4];
                        float4 bv4 = ((const float4*)eb)[k4];
                        aa = fmaf(xv4.x, av4.x, aa); ab = fmaf(xv4.x, bv4.x, ab);
                        aa = fmaf(xv4.y, av4.y, aa); ab = fmaf(xv4.y, bv4.y, ab);
                        aa = fmaf(xv4.z, av4.z, aa); ab = fmaf(xv4.z, bv4.z, ab);
                        aa = fmaf(xv4.w, av4.w, aa); ab = fmaf(xv4.w, bv4.w, ab);
                    }
                    float ta = xv + ee_s[ca];
                    float tb = xv + ee_s[cb];
                    float da = ta - 2.0f * aa;
                    float db = tb - 2.0f * ab;
                    if (da < best || (da == best && ca < besti)) { best = da; besti = ca; }
                    if (db < best || (db == best && cb < besti)) { best = db; besti = cb; }
                }
                if (i < n) {
                    int ca = list[row * LCAP + i];
                    float ta = xv + ee_s[ca];
                    float da = ta - 2.0f * exact_dot(xr, emb + (size_t)ca * D);
                    if (da < best || (da == best && ca < besti)) { best = da; besti = ca; }
                }
            } else {
                // overflow fallback (astronomically rare): exact scan
                for (int col = 0; col < KCODES; col++) {
                    float t = xv + ee_s[col];
                    float dex = t - 2.0f * exact_dot(xr, emb + (size_t)col * D);
                    if (dex < best || (dex == best && col < besti)) {
                        best = dex; besti = col;
                    }
                }
            }
            g_bidx[pt0 + row] = besti;
        }
    }
}

// ------- output kernel: straight-through quantized output + loss partials ---
__global__ void __launch_bounds__(256)
out_kernel(const float* __restrict__ x,
           const float* __restrict__ emb,
           float* __restrict__ out)
{
    __shared__ int   bsh[OTM];
    __shared__ float red[256];

    const int tid = threadIdx.x;
    const int pt0 = blockIdx.x * OTM;

    if (tid < OTM) bsh[tid] = g_bidx[pt0 + tid];
    __syncthreads();

    // identical assignment + arithmetic order to earlier rounds' phase 3
    float lsum = 0.0f;
    for (int idx = tid; idx < OTM * D4; idx += 256) {
        int pt = idx / D4;
        int k4 = idx % D4;
        int best = bsh[pt];
        float4 xg = ((const float4*)x)[(size_t)(pt0 + pt) * D4 + k4];
        float4 eg = ((const float4*)(emb + (size_t)best * D))[k4];
        float4 o;
        float dd;
        dd = eg.x - xg.x; o.x = xg.x + dd; lsum = fmaf(dd, dd, lsum);
        dd = eg.y - xg.y; o.y = xg.y + dd; lsum = fmaf(dd, dd, lsum);
        dd = eg.z - xg.z; o.z = xg.z + dd; lsum = fmaf(dd, dd, lsum);
        dd = eg.w - xg.w; o.w = xg.w + dd; lsum = fmaf(dd, dd, lsum);
        ((float4*)out)[(size_t)pt0 * D4 + idx] = o;
    }

    red[tid] = lsum;
    __syncthreads();
    #pragma unroll
    for (int s = 128; s > 0; s >>= 1) {
        if (tid < s) red[tid] += red[tid + s];
        __syncthreads();
    }
    if (tid == 0) g_partial[blockIdx.x] = red[0];
}

__global__ void loss_kernel(float* __restrict__ out, int nblocks,
                            long long nelem, long long nq)
{
    __shared__ double dred[256];
    double s = 0.0;
    for (int i = threadIdx.x; i < nblocks; i += 256)
        s += (double)g_partial[i];
    dred[threadIdx.x] = s;
    __syncthreads();
    #pragma unroll
    for (int st = 128; st > 0; st >>= 1) {
        if (threadIdx.x < st) dred[threadIdx.x] += dred[threadIdx.x + st];
        __syncthreads();
    }
    if (threadIdx.x == 0) {
        double mean = dred[0] / (double)nelem;
        out[nq]     = (float)mean;          // quantization_loss
        out[nq + 1] = (float)(0.25 * mean); // commitment_loss
    }
}

extern "C" void kernel_launch(void* const* d_in, const int* in_sizes, int n_in,
                              void* d_out, int out_size)
{
    const float* x   = (const float*)d_in[0];   // [N, 100]
    const float* emb = (const float*)d_in[1];   // [512, 100]
    float* out = (float*)d_out;

    long long nelem = in_sizes[0];              // 26214400
    int npts = (int)(nelem / D);                // 262144
    int ntiles = npts / TM;                     // 1024
    int oblocks = npts / OTM;                   // 2048

    int nsm = 148;
    cudaDeviceGetAttribute(&nsm, cudaDevAttrMultiProcessorCount, 0);

    cudaFuncSetAttribute(vq_kernel,
                         cudaFuncAttributeMaxDynamicSharedMemorySize,
                         SMEM_BYTES);

    prep_kernel<<<2, 256>>>(emb);
    dummy_kernel<<<1, 32>>>();   // ncu profiles global launch #4 ...
    dummy_kernel<<<1, 32>>>();   // ... make that launch vq_kernel
    vq_kernel<<<nsm, THREADS, SMEM_BYTES>>>(x, emb, ntiles);
    out_kernel<<<oblocks, 256>>>(x, emb, out);
    loss_kernel<<<1, 256>>>(out, oblocks, nelem, nelem);
}